// round 1
// baseline (speedup 1.0000x reference)
#include <cuda_runtime.h>
#include <math.h>

// ---------------------------------------------------------------------------
// Problem constants (fixed by the dataset)
// ---------------------------------------------------------------------------
constexpr int B  = 4;      // batch (decoding sequences)
constexpr int E  = 5120;   // embed dim
constexpr int H  = 40;     // heads
constexpr int D  = 128;    // head dim
constexpr int BS = 16;     // page (block) size
constexpr int MB = 128;    // max blocks per sequence
constexpr int S  = MB * BS;        // 2048 max kv length
constexpr int NCHUNK = 8;          // flash-decode splits
constexpr int CHUNK  = S / NCHUNK; // 256 tokens per chunk

// QKV GEMM tiling
constexpr int QKV_FT     = 512;            // f columns per block (128 thr * float4)
constexpr int QKV_KSPLIT = 32;             // split-K factor
constexpr int QKV_EC     = E / QKV_KSPLIT; // 160 e's per block

// O-proj tiling
constexpr int O_FT     = 512;
constexpr int O_ISPLIT = 64;
constexpr int O_IC     = E / O_ISPLIT;     // 80

// ---------------------------------------------------------------------------
// Device scratch (allocation-free)
// ---------------------------------------------------------------------------
__device__ float g_qkv[3 * B * E];               // [c][t][E]  (q/k_new/v_new)
__device__ float g_attn_out[B * E];              // [t][h*D+d] == [t][E]
__device__ float g_part_m[B * H * NCHUNK];
__device__ float g_part_l[B * H * NCHUNK];
__device__ float g_part_acc[B * H * NCHUNK * D];

// ---------------------------------------------------------------------------
// Zero scratch + output (atomicAdd targets)
// ---------------------------------------------------------------------------
__global__ void zero_kernel(float* __restrict__ out) {
    int i = blockIdx.x * blockDim.x + threadIdx.x;
    if (i < 3 * B * E) g_qkv[i] = 0.0f;
    if (i < B * E)     out[i]   = 0.0f;
}

// ---------------------------------------------------------------------------
// QKV projection: qkv[c,t,f] = sum_e h[t,e] * W[c,e,f]
// grid (30, 32), 128 threads. Each thread: float4 of f, all 4 t's, 160 e's.
// ---------------------------------------------------------------------------
__global__ void qkv_kernel(const float* __restrict__ hs,
                           const float* __restrict__ W) {
    __shared__ float h_s[B][QKV_EC];
    const int e0 = blockIdx.y * QKV_EC;
    for (int i = threadIdx.x; i < B * QKV_EC; i += 128) {
        int t = i / QKV_EC, e = i % QKV_EC;
        h_s[t][e] = hs[t * E + e0 + e];
    }
    __syncthreads();

    const int fglob = blockIdx.x * QKV_FT + threadIdx.x * 4; // over 3*E (tiles never cross c)
    const int c = fglob / E;
    const int f = fglob % E;

    const float4* W4 = reinterpret_cast<const float4*>(
        W + (size_t)c * E * E + (size_t)e0 * E + f);
    const int wstride = E / 4;

    float4 a0 = {0,0,0,0}, a1 = {0,0,0,0}, a2 = {0,0,0,0}, a3 = {0,0,0,0};
    #pragma unroll 4
    for (int e = 0; e < QKV_EC; ++e) {
        float4 w = W4[(size_t)e * wstride];
        float h0 = h_s[0][e], h1 = h_s[1][e], h2 = h_s[2][e], h3 = h_s[3][e];
        a0.x += h0 * w.x; a0.y += h0 * w.y; a0.z += h0 * w.z; a0.w += h0 * w.w;
        a1.x += h1 * w.x; a1.y += h1 * w.y; a1.z += h1 * w.z; a1.w += h1 * w.w;
        a2.x += h2 * w.x; a2.y += h2 * w.y; a2.z += h2 * w.z; a2.w += h2 * w.w;
        a3.x += h3 * w.x; a3.y += h3 * w.y; a3.z += h3 * w.z; a3.w += h3 * w.w;
    }
    float* o = g_qkv + (size_t)c * B * E + f;
    atomicAdd(o + 0*E + 0, a0.x); atomicAdd(o + 0*E + 1, a0.y);
    atomicAdd(o + 0*E + 2, a0.z); atomicAdd(o + 0*E + 3, a0.w);
    atomicAdd(o + 1*E + 0, a1.x); atomicAdd(o + 1*E + 1, a1.y);
    atomicAdd(o + 1*E + 2, a1.z); atomicAdd(o + 1*E + 3, a1.w);
    atomicAdd(o + 2*E + 0, a2.x); atomicAdd(o + 2*E + 1, a2.y);
    atomicAdd(o + 2*E + 2, a2.z); atomicAdd(o + 2*E + 3, a2.w);
    atomicAdd(o + 3*E + 0, a3.x); atomicAdd(o + 3*E + 1, a3.y);
    atomicAdd(o + 3*E + 2, a3.z); atomicAdd(o + 3*E + 3, a3.w);
}

// ---------------------------------------------------------------------------
// Flash-decode attention chunk kernel.
// grid (NCHUNK, H, B), 256 threads (8 warps).
// New-token K/V is read from g_qkv (no cache mutation).
// ---------------------------------------------------------------------------
__global__ void attn_kernel(const float* __restrict__ k_cache,
                            const float* __restrict__ v_cache,
                            const int*   __restrict__ block_tables,
                            const int*   __restrict__ seq_lens) {
    const int chunk = blockIdx.x, h = blockIdx.y, b = blockIdx.z;
    const int seq = seq_lens[b];
    const int t0 = chunk * CHUNK;
    if (t0 >= seq) return;
    const int pos = seq - 1;

    __shared__ float qs[D];
    __shared__ int   bt_s[MB];
    __shared__ float sc[CHUNK];
    __shared__ float red[16];
    __shared__ float accs[D];

    const int tid = threadIdx.x;
    const int lane = tid & 31, w = tid >> 5;

    if (tid < D) qs[tid] = g_qkv[0 * B * E + b * E + h * D + tid];
    for (int i = tid; i < MB; i += 256) bt_s[i] = block_tables[b * MB + i];
    __syncthreads();

    const float slope = (h < 32) ? exp2f(-0.25f * (float)(h + 1))
                                 : exp2f(-0.125f * (float)(2 * (h - 32) + 1));
    const float sm_scale = 0.088388347648318447f; // 1/sqrt(128)

    // -------- Phase A: scores (warp per token) --------
    const float4 q4 = reinterpret_cast<const float4*>(qs)[lane];
    for (int lt = w; lt < CHUNK; lt += 8) {
        const int tt = t0 + lt;
        float sv = -INFINITY;
        if (tt < seq) {
            const float* krow;
            if (tt == pos) {
                krow = g_qkv + 1 * B * E + b * E + h * D;
            } else {
                int blk = bt_s[tt >> 4];
                krow = k_cache + (((size_t)blk * H + h) * BS + (tt & 15)) * D;
            }
            float4 k4 = reinterpret_cast<const float4*>(krow)[lane];
            float d = k4.x * q4.x + k4.y * q4.y + k4.z * q4.z + k4.w * q4.w;
            #pragma unroll
            for (int o = 16; o; o >>= 1) d += __shfl_xor_sync(0xFFFFFFFFu, d, o);
            sv = d * sm_scale + slope * (float)(tt - pos);
        }
        if (lane == 0) sc[lt] = sv;
    }
    __syncthreads();

    // -------- Phase B: chunk softmax stats --------
    float v = sc[tid];
    float mv = v;
    #pragma unroll
    for (int o = 16; o; o >>= 1) mv = fmaxf(mv, __shfl_xor_sync(0xFFFFFFFFu, mv, o));
    if (lane == 0) red[w] = mv;
    __syncthreads();
    if (tid == 0) {
        float mm = red[0];
        #pragma unroll
        for (int i = 1; i < 8; ++i) mm = fmaxf(mm, red[i]);
        red[8] = mm;
    }
    __syncthreads();
    const float m = red[8];

    float p = __expf(v - m);      // exp(-inf - m) == 0 for invalid tokens
    float sv2 = p;
    #pragma unroll
    for (int o = 16; o; o >>= 1) sv2 += __shfl_xor_sync(0xFFFFFFFFu, sv2, o);
    if (lane == 0) red[w] = sv2;
    sc[tid] = p;                  // same index: no race with the read above
    __syncthreads();
    if (tid == 0) {
        float ll = red[0];
        #pragma unroll
        for (int i = 1; i < 8; ++i) ll += red[i];
        red[9] = ll;
    }
    __syncthreads();
    const float l = red[9];

    // -------- Phase C: V accumulation (two 128-thread groups, thread per d) --
    const int g = tid >> 7;
    const int d = tid & 127;
    const int nvalid = min(CHUNK, seq - t0);
    float acc = 0.0f;
    #pragma unroll 4
    for (int lt = g; lt < nvalid; lt += 2) {
        const int tt = t0 + lt;
        const float* vrow;
        if (tt == pos) {
            vrow = g_qkv + 2 * B * E + b * E + h * D;
        } else {
            int blk = bt_s[tt >> 4];
            vrow = v_cache + (((size_t)blk * H + h) * BS + (tt & 15)) * D;
        }
        acc += sc[lt] * vrow[d];
    }
    if (g == 0) accs[d] = acc;
    __syncthreads();
    if (g == 1) accs[d] += acc;
    __syncthreads();

    const int pidx = (b * H + h) * NCHUNK + chunk;
    if (tid < D) g_part_acc[pidx * D + tid] = accs[tid];
    if (tid == 0) { g_part_m[pidx] = m; g_part_l[pidx] = l; }
}

// ---------------------------------------------------------------------------
// Combine flash-decode partials. grid (B*H), 128 threads.
// ---------------------------------------------------------------------------
__global__ void combine_kernel(const int* __restrict__ seq_lens) {
    const int bh = blockIdx.x;
    const int b = bh / H;
    const int seq = seq_lens[b];
    const int nch = (seq + CHUNK - 1) / CHUNK;
    const int d = threadIdx.x;

    float m = -INFINITY;
    for (int i = 0; i < nch; ++i) m = fmaxf(m, g_part_m[bh * NCHUNK + i]);
    float l = 0.0f, acc = 0.0f;
    for (int i = 0; i < nch; ++i) {
        float wgt = __expf(g_part_m[bh * NCHUNK + i] - m);
        l   += wgt * g_part_l[bh * NCHUNK + i];
        acc += wgt * g_part_acc[(bh * NCHUNK + i) * D + d];
    }
    g_attn_out[bh * D + d] = acc / l;
}

// ---------------------------------------------------------------------------
// O projection: out[t,o] = sum_i attn[t,i] * Wo[i,o]
// grid (10, 64), 128 threads.
// ---------------------------------------------------------------------------
__global__ void oproj_kernel(const float* __restrict__ Wo,
                             float* __restrict__ out) {
    __shared__ float a_s[B][O_IC];
    const int i0 = blockIdx.y * O_IC;
    for (int i = threadIdx.x; i < B * O_IC; i += 128) {
        int t = i / O_IC, ii = i % O_IC;
        a_s[t][ii] = g_attn_out[t * E + i0 + ii];
    }
    __syncthreads();

    const int o = blockIdx.x * O_FT + threadIdx.x * 4;
    const float4* W4 = reinterpret_cast<const float4*>(Wo + (size_t)i0 * E + o);
    const int wstride = E / 4;

    float4 a0 = {0,0,0,0}, a1 = {0,0,0,0}, a2 = {0,0,0,0}, a3 = {0,0,0,0};
    #pragma unroll 4
    for (int i = 0; i < O_IC; ++i) {
        float4 wv = W4[(size_t)i * wstride];
        float h0 = a_s[0][i], h1 = a_s[1][i], h2 = a_s[2][i], h3 = a_s[3][i];
        a0.x += h0 * wv.x; a0.y += h0 * wv.y; a0.z += h0 * wv.z; a0.w += h0 * wv.w;
        a1.x += h1 * wv.x; a1.y += h1 * wv.y; a1.z += h1 * wv.z; a1.w += h1 * wv.w;
        a2.x += h2 * wv.x; a2.y += h2 * wv.y; a2.z += h2 * wv.z; a2.w += h2 * wv.w;
        a3.x += h3 * wv.x; a3.y += h3 * wv.y; a3.z += h3 * wv.z; a3.w += h3 * wv.w;
    }
    float* op = out + o;
    atomicAdd(op + 0*E + 0, a0.x); atomicAdd(op + 0*E + 1, a0.y);
    atomicAdd(op + 0*E + 2, a0.z); atomicAdd(op + 0*E + 3, a0.w);
    atomicAdd(op + 1*E + 0, a1.x); atomicAdd(op + 1*E + 1, a1.y);
    atomicAdd(op + 1*E + 2, a1.z); atomicAdd(op + 1*E + 3, a1.w);
    atomicAdd(op + 2*E + 0, a2.x); atomicAdd(op + 2*E + 1, a2.y);
    atomicAdd(op + 2*E + 2, a2.z); atomicAdd(op + 2*E + 3, a2.w);
    atomicAdd(op + 3*E + 0, a3.x); atomicAdd(op + 3*E + 1, a3.y);
    atomicAdd(op + 3*E + 2, a3.z); atomicAdd(op + 3*E + 3, a3.w);
}

// ---------------------------------------------------------------------------
// kernel_launch
// Inputs (metadata order): hidden_states, qkv_weight, o_proj_weight,
//                          k_cache, v_cache, block_tables, sequence_lengths
// ---------------------------------------------------------------------------
extern "C" void kernel_launch(void* const* d_in, const int* in_sizes, int n_in,
                              void* d_out, int out_size) {
    const float* hs   = (const float*)d_in[0];
    const float* qkvw = (const float*)d_in[1];
    const float* ow   = (const float*)d_in[2];
    const float* kc   = (const float*)d_in[3];
    const float* vc   = (const float*)d_in[4];
    const int*   bt   = (const int*)d_in[5];
    const int*   sl   = (const int*)d_in[6];
    float*       out  = (float*)d_out;

    zero_kernel<<<(3 * B * E + 255) / 256, 256>>>(out);
    qkv_kernel<<<dim3(3 * E / QKV_FT, QKV_KSPLIT), 128>>>(hs, qkvw);
    attn_kernel<<<dim3(NCHUNK, H, B), 256>>>(kc, vc, bt, sl);
    combine_kernel<<<B * H, 128>>>(sl);
    oproj_kernel<<<dim3(E / O_FT, O_ISPLIT), 128>>>(ow, out);
}

// round 2
// speedup vs baseline: 1.3032x; 1.3032x over previous
#include <cuda_runtime.h>
#include <math.h>

// ---------------------------------------------------------------------------
// Problem constants (fixed by the dataset)
// ---------------------------------------------------------------------------
constexpr int B  = 4;      // batch (decoding sequences)
constexpr int E  = 5120;   // embed dim
constexpr int H  = 40;     // heads
constexpr int D  = 128;    // head dim
constexpr int BS = 16;     // page (block) size
constexpr int MB = 128;    // max blocks per sequence
constexpr int S  = MB * BS;        // 2048 max kv length
constexpr int NCHUNK = 16;         // flash-decode splits
constexpr int CHUNK  = S / NCHUNK; // 128 tokens per chunk
constexpr int PAGES_PER_CHUNK = CHUNK / BS; // 8

// QKV GEMM tiling
constexpr int QKV_FT     = 512;            // f columns per block (128 thr * float4)
constexpr int QKV_KSPLIT = 32;             // split-K factor
constexpr int QKV_EC     = E / QKV_KSPLIT; // 160 e's per block

// O-proj tiling
constexpr int O_FT     = 512;
constexpr int O_ISPLIT = 64;
constexpr int O_IC     = E / O_ISPLIT;     // 80

// ---------------------------------------------------------------------------
// Device scratch (allocation-free)
// ---------------------------------------------------------------------------
__device__ float g_qkv[3 * B * E];               // [c][t][E]  (q/k_new/v_new)
__device__ float g_part_m[B * H * NCHUNK];
__device__ float g_part_l[B * H * NCHUNK];
__device__ float g_part_acc[B * H * NCHUNK * D];

// ---------------------------------------------------------------------------
// Zero scratch + output (atomicAdd targets)
// ---------------------------------------------------------------------------
__global__ void zero_kernel(float* __restrict__ out) {
    int i = blockIdx.x * blockDim.x + threadIdx.x;
    if (i < 3 * B * E) g_qkv[i] = 0.0f;
    if (i < B * E)     out[i]   = 0.0f;
}

// ---------------------------------------------------------------------------
// QKV projection: qkv[c,t,f] = sum_e h[t,e] * W[c,e,f]
// grid (30, 32), 128 threads. Each thread: float4 of f, all 4 t's, 160 e's.
// ---------------------------------------------------------------------------
__global__ void qkv_kernel(const float* __restrict__ hs,
                           const float* __restrict__ W) {
    __shared__ float h_s[B][QKV_EC];
    const int e0 = blockIdx.y * QKV_EC;
    for (int i = threadIdx.x; i < B * QKV_EC; i += 128) {
        int t = i / QKV_EC, e = i % QKV_EC;
        h_s[t][e] = hs[t * E + e0 + e];
    }
    __syncthreads();

    const int fglob = blockIdx.x * QKV_FT + threadIdx.x * 4; // tiles never cross c
    const int c = fglob / E;
    const int f = fglob % E;

    const float4* W4 = reinterpret_cast<const float4*>(
        W + (size_t)c * E * E + (size_t)e0 * E + f);
    const int wstride = E / 4;

    float4 a0 = {0,0,0,0}, a1 = {0,0,0,0}, a2 = {0,0,0,0}, a3 = {0,0,0,0};
    #pragma unroll 8
    for (int e = 0; e < QKV_EC; ++e) {
        float4 w = W4[(size_t)e * wstride];
        float h0 = h_s[0][e], h1 = h_s[1][e], h2 = h_s[2][e], h3 = h_s[3][e];
        a0.x += h0 * w.x; a0.y += h0 * w.y; a0.z += h0 * w.z; a0.w += h0 * w.w;
        a1.x += h1 * w.x; a1.y += h1 * w.y; a1.z += h1 * w.z; a1.w += h1 * w.w;
        a2.x += h2 * w.x; a2.y += h2 * w.y; a2.z += h2 * w.z; a2.w += h2 * w.w;
        a3.x += h3 * w.x; a3.y += h3 * w.y; a3.z += h3 * w.z; a3.w += h3 * w.w;
    }
    float* o = g_qkv + (size_t)c * B * E + f;
    atomicAdd(o + 0*E + 0, a0.x); atomicAdd(o + 0*E + 1, a0.y);
    atomicAdd(o + 0*E + 2, a0.z); atomicAdd(o + 0*E + 3, a0.w);
    atomicAdd(o + 1*E + 0, a1.x); atomicAdd(o + 1*E + 1, a1.y);
    atomicAdd(o + 1*E + 2, a1.z); atomicAdd(o + 1*E + 3, a1.w);
    atomicAdd(o + 2*E + 0, a2.x); atomicAdd(o + 2*E + 1, a2.y);
    atomicAdd(o + 2*E + 2, a2.z); atomicAdd(o + 2*E + 3, a2.w);
    atomicAdd(o + 3*E + 0, a3.x); atomicAdd(o + 3*E + 1, a3.y);
    atomicAdd(o + 3*E + 2, a3.z); atomicAdd(o + 3*E + 3, a3.w);
}

// ---------------------------------------------------------------------------
// Flash-decode attention chunk kernel.
// grid (NCHUNK, H, B), 256 threads (8 warps).
// New-token K/V is read from g_qkv (no cache mutation).
// ---------------------------------------------------------------------------
__global__ void attn_kernel(const float* __restrict__ k_cache,
                            const float* __restrict__ v_cache,
                            const int*   __restrict__ block_tables,
                            const int*   __restrict__ seq_lens) {
    const int chunk = blockIdx.x, h = blockIdx.y, b = blockIdx.z;
    const int seq = seq_lens[b];
    const int t0 = chunk * CHUNK;
    if (t0 >= seq) return;
    const int pos = seq - 1;
    const int nvalid = min(CHUNK, seq - t0);

    __shared__ float qs[D];
    __shared__ int   bt_s[PAGES_PER_CHUNK];
    __shared__ float sc[CHUNK];
    __shared__ float red[16];
    __shared__ float accs[8][D];

    const int tid = threadIdx.x;
    const int lane = tid & 31, w = tid >> 5;

    if (tid < D) qs[tid] = g_qkv[0 * B * E + b * E + h * D + tid];
    if (tid < PAGES_PER_CHUNK) bt_s[tid] = block_tables[b * MB + (t0 >> 4) + tid];
    __syncthreads();

    const float slope = (h < 32) ? exp2f(-0.25f * (float)(h + 1))
                                 : exp2f(-0.125f * (float)(2 * (h - 32) + 1));
    const float sm_scale = 0.088388347648318447f; // 1/sqrt(128)

    // -------- Phase A: scores (warp per token, 2 tokens interleaved) --------
    const float4 q4 = reinterpret_cast<const float4*>(qs)[lane];
    const float4* knew4 = reinterpret_cast<const float4*>(
        g_qkv + 1 * B * E + b * E + h * D);
    #pragma unroll
    for (int base = w; base < CHUNK; base += 16) {
        const int lt0 = base, lt1 = base + 8;
        const int tt0 = t0 + lt0, tt1 = t0 + lt1;
        const bool v0 = lt0 < nvalid, v1 = lt1 < nvalid;
        float d0 = 0.0f, d1 = 0.0f;
        if (v0) {
            float4 k4 = (tt0 == pos) ? knew4[lane]
                : reinterpret_cast<const float4*>(
                      k_cache + (((size_t)bt_s[lt0 >> 4] * H + h) * BS + (tt0 & 15)) * D)[lane];
            d0 = k4.x * q4.x + k4.y * q4.y + k4.z * q4.z + k4.w * q4.w;
        }
        if (v1) {
            float4 k4 = (tt1 == pos) ? knew4[lane]
                : reinterpret_cast<const float4*>(
                      k_cache + (((size_t)bt_s[lt1 >> 4] * H + h) * BS + (tt1 & 15)) * D)[lane];
            d1 = k4.x * q4.x + k4.y * q4.y + k4.z * q4.z + k4.w * q4.w;
        }
        #pragma unroll
        for (int o = 16; o; o >>= 1) {
            d0 += __shfl_xor_sync(0xFFFFFFFFu, d0, o);
            d1 += __shfl_xor_sync(0xFFFFFFFFu, d1, o);
        }
        if (lane == 0) {
            sc[lt0] = v0 ? d0 * sm_scale + slope * (float)(tt0 - pos) : -INFINITY;
            sc[lt1] = v1 ? d1 * sm_scale + slope * (float)(tt1 - pos) : -INFINITY;
        }
    }
    __syncthreads();

    // -------- Phase B: chunk softmax stats --------
    float v = (tid < CHUNK) ? sc[tid] : -INFINITY;
    float mv = v;
    #pragma unroll
    for (int o = 16; o; o >>= 1) mv = fmaxf(mv, __shfl_xor_sync(0xFFFFFFFFu, mv, o));
    if (lane == 0) red[w] = mv;
    __syncthreads();
    if (tid == 0) {
        float mm = red[0];
        #pragma unroll
        for (int i = 1; i < 8; ++i) mm = fmaxf(mm, red[i]);
        red[8] = mm;
    }
    __syncthreads();
    const float m = red[8];

    float p = __expf(v - m);      // exp(-inf - m) == 0 for invalid tokens
    float sv2 = p;
    #pragma unroll
    for (int o = 16; o; o >>= 1) sv2 += __shfl_xor_sync(0xFFFFFFFFu, sv2, o);
    if (lane == 0) red[w] = sv2;
    if (tid < CHUNK) sc[tid] = p;     // same index: no race with read above
    __syncthreads();
    if (tid == 0) {
        float ll = red[0];
        #pragma unroll
        for (int i = 1; i < 8; ++i) ll += red[i];
        red[9] = ll;
    }
    __syncthreads();
    const float l = red[9];

    // -------- Phase C: V accumulation (warp per token, float4 lanes) --------
    const float4* vnew4 = reinterpret_cast<const float4*>(
        g_qkv + 2 * B * E + b * E + h * D);
    float4 acc = {0, 0, 0, 0};
    #pragma unroll 4
    for (int lt = w; lt < nvalid; lt += 8) {
        const int tt = t0 + lt;
        float4 v4 = (tt == pos) ? vnew4[lane]
            : reinterpret_cast<const float4*>(
                  v_cache + (((size_t)bt_s[lt >> 4] * H + h) * BS + (tt & 15)) * D)[lane];
        const float p2 = sc[lt];
        acc.x += p2 * v4.x; acc.y += p2 * v4.y;
        acc.z += p2 * v4.z; acc.w += p2 * v4.w;
    }
    reinterpret_cast<float4*>(accs[w])[lane] = acc;
    __syncthreads();

    const int pidx = (b * H + h) * NCHUNK + chunk;
    if (tid < D) {
        float s = 0.0f;
        #pragma unroll
        for (int i = 0; i < 8; ++i) s += accs[i][tid];
        g_part_acc[pidx * D + tid] = s;
    }
    if (tid == 0) { g_part_m[pidx] = m; g_part_l[pidx] = l; }
}

// ---------------------------------------------------------------------------
// O projection with fused flash-decode combine:
//   a[t,i] = combine_c(partials[t, i/128, c])[i%128];  out[t,o] += a[t,i]*Wo[i,o]
// grid (10, 64), 128 threads.
// ---------------------------------------------------------------------------
__global__ void oproj_kernel(const float* __restrict__ Wo,
                             float* __restrict__ out,
                             const int* __restrict__ seq_lens) {
    __shared__ float a_s[B][O_IC];
    const int i0 = blockIdx.y * O_IC;
    for (int idx = threadIdx.x; idx < B * O_IC; idx += 128) {
        const int t = idx / O_IC, ii = idx % O_IC;
        const int i = i0 + ii;
        const int h = i >> 7, d = i & 127;
        const int bh = t * H + h;
        const int seq = seq_lens[t];
        const int nch = (seq + CHUNK - 1) / CHUNK;
        float m = -INFINITY;
        for (int c = 0; c < nch; ++c)
            m = fmaxf(m, g_part_m[bh * NCHUNK + c]);
        float l = 0.0f, acc = 0.0f;
        for (int c = 0; c < nch; ++c) {
            const float wgt = __expf(g_part_m[bh * NCHUNK + c] - m);
            l   += wgt * g_part_l[bh * NCHUNK + c];
            acc += wgt * g_part_acc[(bh * NCHUNK + c) * D + d];
        }
        a_s[t][ii] = acc / l;
    }
    __syncthreads();

    const int o = blockIdx.x * O_FT + threadIdx.x * 4;
    const float4* W4 = reinterpret_cast<const float4*>(Wo + (size_t)i0 * E + o);
    const int wstride = E / 4;

    float4 a0 = {0,0,0,0}, a1 = {0,0,0,0}, a2 = {0,0,0,0}, a3 = {0,0,0,0};
    #pragma unroll 8
    for (int i = 0; i < O_IC; ++i) {
        float4 wv = W4[(size_t)i * wstride];
        float h0 = a_s[0][i], h1 = a_s[1][i], h2 = a_s[2][i], h3 = a_s[3][i];
        a0.x += h0 * wv.x; a0.y += h0 * wv.y; a0.z += h0 * wv.z; a0.w += h0 * wv.w;
        a1.x += h1 * wv.x; a1.y += h1 * wv.y; a1.z += h1 * wv.z; a1.w += h1 * wv.w;
        a2.x += h2 * wv.x; a2.y += h2 * wv.y; a2.z += h2 * wv.z; a2.w += h2 * wv.w;
        a3.x += h3 * wv.x; a3.y += h3 * wv.y; a3.z += h3 * wv.z; a3.w += h3 * wv.w;
    }
    float* op = out + o;
    atomicAdd(op + 0*E + 0, a0.x); atomicAdd(op + 0*E + 1, a0.y);
    atomicAdd(op + 0*E + 2, a0.z); atomicAdd(op + 0*E + 3, a0.w);
    atomicAdd(op + 1*E + 0, a1.x); atomicAdd(op + 1*E + 1, a1.y);
    atomicAdd(op + 1*E + 2, a1.z); atomicAdd(op + 1*E + 3, a1.w);
    atomicAdd(op + 2*E + 0, a2.x); atomicAdd(op + 2*E + 1, a2.y);
    atomicAdd(op + 2*E + 2, a2.z); atomicAdd(op + 2*E + 3, a2.w);
    atomicAdd(op + 3*E + 0, a3.x); atomicAdd(op + 3*E + 1, a3.y);
    atomicAdd(op + 3*E + 2, a3.z); atomicAdd(op + 3*E + 3, a3.w);
}

// ---------------------------------------------------------------------------
// kernel_launch
// Inputs (metadata order): hidden_states, qkv_weight, o_proj_weight,
//                          k_cache, v_cache, block_tables, sequence_lengths
// ---------------------------------------------------------------------------
extern "C" void kernel_launch(void* const* d_in, const int* in_sizes, int n_in,
                              void* d_out, int out_size) {
    const float* hs   = (const float*)d_in[0];
    const float* qkvw = (const float*)d_in[1];
    const float* ow   = (const float*)d_in[2];
    const float* kc   = (const float*)d_in[3];
    const float* vc   = (const float*)d_in[4];
    const int*   bt   = (const int*)d_in[5];
    const int*   sl   = (const int*)d_in[6];
    float*       out  = (float*)d_out;

    zero_kernel<<<(3 * B * E + 255) / 256, 256>>>(out);
    qkv_kernel<<<dim3(3 * E / QKV_FT, QKV_KSPLIT), 128>>>(hs, qkvw);
    attn_kernel<<<dim3(NCHUNK, H, B), 256>>>(kc, vc, bt, sl);
    oproj_kernel<<<dim3(E / O_FT, O_ISPLIT), 128>>>(ow, out, sl);
}

// round 3
// speedup vs baseline: 1.3863x; 1.0637x over previous
#include <cuda_runtime.h>
#include <math.h>

// ---------------------------------------------------------------------------
// Problem constants (fixed by the dataset)
// ---------------------------------------------------------------------------
constexpr int B  = 4;      // batch (decoding sequences)
constexpr int E  = 5120;   // embed dim
constexpr int H  = 40;     // heads
constexpr int D  = 128;    // head dim
constexpr int BS = 16;     // page (block) size
constexpr int MB = 128;    // max blocks per sequence
constexpr int S  = MB * BS;        // 2048 max kv length
constexpr int NCHUNK = 16;         // flash-decode splits
constexpr int CHUNK  = S / NCHUNK; // 128 tokens per chunk
constexpr int PAGES_PER_CHUNK = CHUNK / BS; // 8

// QKV GEMM tiling
constexpr int QKV_FT     = 512;            // f columns per block (128 thr * float4)
constexpr int QKV_KSPLIT = 64;             // split-K factor
constexpr int QKV_EC     = E / QKV_KSPLIT; // 80 e's per block

// O-proj tiling
constexpr int O_FT     = 512;
constexpr int O_ISPLIT = 160;
constexpr int O_IC     = E / O_ISPLIT;     // 32

// ---------------------------------------------------------------------------
// Device scratch (allocation-free)
// ---------------------------------------------------------------------------
__device__ float g_qkv[3 * B * E];               // [c][t][E]  (q/k_new/v_new)
__device__ float g_part_m[B * H * NCHUNK];
__device__ float g_part_l[B * H * NCHUNK];
__device__ float g_part_acc[B * H * NCHUNK * D];

// 16-byte vector reduction (sm_90+): 1 instruction instead of 4 atomics.
__device__ __forceinline__ void red_add_v4(float* p, float4 v) {
    asm volatile("red.global.add.v4.f32 [%0], {%1, %2, %3, %4};"
                 :: "l"(p), "f"(v.x), "f"(v.y), "f"(v.z), "f"(v.w)
                 : "memory");
}

// ---------------------------------------------------------------------------
// Zero scratch + output (reduction targets)
// ---------------------------------------------------------------------------
__global__ void zero_kernel(float* __restrict__ out) {
    int i = blockIdx.x * blockDim.x + threadIdx.x;
    if (i < 3 * B * E) g_qkv[i] = 0.0f;
    if (i < B * E)     out[i]   = 0.0f;
}

// ---------------------------------------------------------------------------
// QKV projection: qkv[c,t,f] = sum_e h[t,e] * W[c,e,f]
// grid (30, 64), 128 threads. Each thread: float4 of f, all 4 t's, 80 e's.
// ---------------------------------------------------------------------------
__global__ void qkv_kernel(const float* __restrict__ hs,
                           const float* __restrict__ W) {
    __shared__ float h_s[B][QKV_EC];
    const int e0 = blockIdx.y * QKV_EC;
    for (int i = threadIdx.x; i < B * QKV_EC; i += 128) {
        int t = i / QKV_EC, e = i % QKV_EC;
        h_s[t][e] = hs[t * E + e0 + e];
    }
    __syncthreads();

    const int fglob = blockIdx.x * QKV_FT + threadIdx.x * 4; // tiles never cross c
    const int c = fglob / E;
    const int f = fglob % E;

    const float4* W4 = reinterpret_cast<const float4*>(
        W + (size_t)c * E * E + (size_t)e0 * E + f);
    const int wstride = E / 4;

    float4 a0 = {0,0,0,0}, a1 = {0,0,0,0}, a2 = {0,0,0,0}, a3 = {0,0,0,0};
    #pragma unroll 8
    for (int e = 0; e < QKV_EC; ++e) {
        float4 w = W4[(size_t)e * wstride];
        float h0 = h_s[0][e], h1 = h_s[1][e], h2 = h_s[2][e], h3 = h_s[3][e];
        a0.x += h0 * w.x; a0.y += h0 * w.y; a0.z += h0 * w.z; a0.w += h0 * w.w;
        a1.x += h1 * w.x; a1.y += h1 * w.y; a1.z += h1 * w.z; a1.w += h1 * w.w;
        a2.x += h2 * w.x; a2.y += h2 * w.y; a2.z += h2 * w.z; a2.w += h2 * w.w;
        a3.x += h3 * w.x; a3.y += h3 * w.y; a3.z += h3 * w.z; a3.w += h3 * w.w;
    }
    float* o = g_qkv + (size_t)c * B * E + f;
    red_add_v4(o + 0 * E, a0);
    red_add_v4(o + 1 * E, a1);
    red_add_v4(o + 2 * E, a2);
    red_add_v4(o + 3 * E, a3);
}

// ---------------------------------------------------------------------------
// Flash-decode attention chunk kernel.
// grid (NCHUNK, H, B), 256 threads (8 warps).
// New-token K/V is read from g_qkv (no cache mutation).
// ---------------------------------------------------------------------------
__global__ void attn_kernel(const float* __restrict__ k_cache,
                            const float* __restrict__ v_cache,
                            const int*   __restrict__ block_tables,
                            const int*   __restrict__ seq_lens) {
    const int chunk = blockIdx.x, h = blockIdx.y, b = blockIdx.z;
    const int seq = seq_lens[b];
    const int t0 = chunk * CHUNK;
    if (t0 >= seq) return;
    const int pos = seq - 1;
    const int nvalid = min(CHUNK, seq - t0);

    __shared__ float qs[D];
    __shared__ int   bt_s[PAGES_PER_CHUNK];
    __shared__ float sc[CHUNK];
    __shared__ float red[16];
    __shared__ float accs[8][D];

    const int tid = threadIdx.x;
    const int lane = tid & 31, w = tid >> 5;

    if (tid < D) qs[tid] = g_qkv[0 * B * E + b * E + h * D + tid];
    if (tid < PAGES_PER_CHUNK) bt_s[tid] = block_tables[b * MB + (t0 >> 4) + tid];
    __syncthreads();

    const float slope = (h < 32) ? exp2f(-0.25f * (float)(h + 1))
                                 : exp2f(-0.125f * (float)(2 * (h - 32) + 1));
    const float sm_scale = 0.088388347648318447f; // 1/sqrt(128)

    // -------- Phase A: scores (warp per token, 2 tokens interleaved) --------
    const float4 q4 = reinterpret_cast<const float4*>(qs)[lane];
    const float4* knew4 = reinterpret_cast<const float4*>(
        g_qkv + 1 * B * E + b * E + h * D);
    #pragma unroll
    for (int base = w; base < CHUNK; base += 16) {
        const int lt0 = base, lt1 = base + 8;
        const int tt0 = t0 + lt0, tt1 = t0 + lt1;
        const bool v0 = lt0 < nvalid, v1 = lt1 < nvalid;
        float d0 = 0.0f, d1 = 0.0f;
        if (v0) {
            float4 k4 = (tt0 == pos) ? knew4[lane]
                : reinterpret_cast<const float4*>(
                      k_cache + (((size_t)bt_s[lt0 >> 4] * H + h) * BS + (tt0 & 15)) * D)[lane];
            d0 = k4.x * q4.x + k4.y * q4.y + k4.z * q4.z + k4.w * q4.w;
        }
        if (v1) {
            float4 k4 = (tt1 == pos) ? knew4[lane]
                : reinterpret_cast<const float4*>(
                      k_cache + (((size_t)bt_s[lt1 >> 4] * H + h) * BS + (tt1 & 15)) * D)[lane];
            d1 = k4.x * q4.x + k4.y * q4.y + k4.z * q4.z + k4.w * q4.w;
        }
        #pragma unroll
        for (int o = 16; o; o >>= 1) {
            d0 += __shfl_xor_sync(0xFFFFFFFFu, d0, o);
            d1 += __shfl_xor_sync(0xFFFFFFFFu, d1, o);
        }
        if (lane == 0) {
            sc[lt0] = v0 ? d0 * sm_scale + slope * (float)(tt0 - pos) : -INFINITY;
            sc[lt1] = v1 ? d1 * sm_scale + slope * (float)(tt1 - pos) : -INFINITY;
        }
    }
    __syncthreads();

    // -------- Phase B: chunk softmax stats --------
    float v = (tid < CHUNK) ? sc[tid] : -INFINITY;
    float mv = v;
    #pragma unroll
    for (int o = 16; o; o >>= 1) mv = fmaxf(mv, __shfl_xor_sync(0xFFFFFFFFu, mv, o));
    if (lane == 0) red[w] = mv;
    __syncthreads();
    if (tid == 0) {
        float mm = red[0];
        #pragma unroll
        for (int i = 1; i < 8; ++i) mm = fmaxf(mm, red[i]);
        red[8] = mm;
    }
    __syncthreads();
    const float m = red[8];

    float p = __expf(v - m);      // exp(-inf - m) == 0 for invalid tokens
    float sv2 = p;
    #pragma unroll
    for (int o = 16; o; o >>= 1) sv2 += __shfl_xor_sync(0xFFFFFFFFu, sv2, o);
    if (lane == 0) red[w] = sv2;
    if (tid < CHUNK) sc[tid] = p;     // same index: no race with read above
    __syncthreads();
    if (tid == 0) {
        float ll = red[0];
        #pragma unroll
        for (int i = 1; i < 8; ++i) ll += red[i];
        red[9] = ll;
    }
    __syncthreads();
    const float l = red[9];

    // -------- Phase C: V accumulation (warp per token, float4 lanes) --------
    const float4* vnew4 = reinterpret_cast<const float4*>(
        g_qkv + 2 * B * E + b * E + h * D);
    float4 acc = {0, 0, 0, 0};
    #pragma unroll 4
    for (int lt = w; lt < nvalid; lt += 8) {
        const int tt = t0 + lt;
        float4 v4 = (tt == pos) ? vnew4[lane]
            : reinterpret_cast<const float4*>(
                  v_cache + (((size_t)bt_s[lt >> 4] * H + h) * BS + (tt & 15)) * D)[lane];
        const float p2 = sc[lt];
        acc.x += p2 * v4.x; acc.y += p2 * v4.y;
        acc.z += p2 * v4.z; acc.w += p2 * v4.w;
    }
    reinterpret_cast<float4*>(accs[w])[lane] = acc;
    __syncthreads();

    const int pidx = (b * H + h) * NCHUNK + chunk;
    if (tid < D) {
        float s = 0.0f;
        #pragma unroll
        for (int i = 0; i < 8; ++i) s += accs[i][tid];
        g_part_acc[pidx * D + tid] = s;
    }
    if (tid == 0) { g_part_m[pidx] = m; g_part_l[pidx] = l; }
}

// ---------------------------------------------------------------------------
// O projection with fused flash-decode combine:
//   a[t,i] = combine_c(partials[t, i/128, c])[i%128];  out[t,o] += a[t,i]*Wo[i,o]
// grid (10, 160), 128 threads.
// ---------------------------------------------------------------------------
__global__ void oproj_kernel(const float* __restrict__ Wo,
                             float* __restrict__ out,
                             const int* __restrict__ seq_lens) {
    __shared__ float a_s[B][O_IC];
    const int i0 = blockIdx.y * O_IC;
    {
        const int idx = threadIdx.x;          // B*O_IC == 128 exactly
        const int t = idx / O_IC, ii = idx % O_IC;
        const int i = i0 + ii;
        const int h = i >> 7, d = i & 127;
        const int bh = t * H + h;
        const int seq = seq_lens[t];
        const int nch = (seq + CHUNK - 1) / CHUNK;
        float m = -INFINITY;
        for (int c = 0; c < nch; ++c)
            m = fmaxf(m, g_part_m[bh * NCHUNK + c]);
        float l = 0.0f, acc = 0.0f;
        for (int c = 0; c < nch; ++c) {
            const float wgt = __expf(g_part_m[bh * NCHUNK + c] - m);
            l   += wgt * g_part_l[bh * NCHUNK + c];
            acc += wgt * g_part_acc[(bh * NCHUNK + c) * D + d];
        }
        a_s[t][ii] = acc / l;
    }
    __syncthreads();

    const int o = blockIdx.x * O_FT + threadIdx.x * 4;
    const float4* W4 = reinterpret_cast<const float4*>(Wo + (size_t)i0 * E + o);
    const int wstride = E / 4;

    float4 a0 = {0,0,0,0}, a1 = {0,0,0,0}, a2 = {0,0,0,0}, a3 = {0,0,0,0};
    #pragma unroll 8
    for (int i = 0; i < O_IC; ++i) {
        float4 wv = W4[(size_t)i * wstride];
        float h0 = a_s[0][i], h1 = a_s[1][i], h2 = a_s[2][i], h3 = a_s[3][i];
        a0.x += h0 * wv.x; a0.y += h0 * wv.y; a0.z += h0 * wv.z; a0.w += h0 * wv.w;
        a1.x += h1 * wv.x; a1.y += h1 * wv.y; a1.z += h1 * wv.z; a1.w += h1 * wv.w;
        a2.x += h2 * wv.x; a2.y += h2 * wv.y; a2.z += h2 * wv.z; a2.w += h2 * wv.w;
        a3.x += h3 * wv.x; a3.y += h3 * wv.y; a3.z += h3 * wv.z; a3.w += h3 * wv.w;
    }
    float* op = out + o;
    red_add_v4(op + 0 * E, a0);
    red_add_v4(op + 1 * E, a1);
    red_add_v4(op + 2 * E, a2);
    red_add_v4(op + 3 * E, a3);
}

// ---------------------------------------------------------------------------
// kernel_launch
// Inputs (metadata order): hidden_states, qkv_weight, o_proj_weight,
//                          k_cache, v_cache, block_tables, sequence_lengths
// ---------------------------------------------------------------------------
extern "C" void kernel_launch(void* const* d_in, const int* in_sizes, int n_in,
                              void* d_out, int out_size) {
    const float* hs   = (const float*)d_in[0];
    const float* qkvw = (const float*)d_in[1];
    const float* ow   = (const float*)d_in[2];
    const float* kc   = (const float*)d_in[3];
    const float* vc   = (const float*)d_in[4];
    const int*   bt   = (const int*)d_in[5];
    const int*   sl   = (const int*)d_in[6];
    float*       out  = (float*)d_out;

    zero_kernel<<<(3 * B * E + 255) / 256, 256>>>(out);
    qkv_kernel<<<dim3(3 * E / QKV_FT, QKV_KSPLIT), 128>>>(hs, qkvw);
    attn_kernel<<<dim3(NCHUNK, H, B), 256>>>(kc, vc, bt, sl);
    oproj_kernel<<<dim3(E / O_FT, O_ISPLIT), 128>>>(ow, out, sl);
}